// round 13
// baseline (speedup 1.0000x reference)
#include <cuda_runtime.h>
#include <cuda_bf16.h>
#include <cuda_fp16.h>
#include <math.h>
#include <stdint.h>

#define NB 8
#define BATCH 256
#define NV 14062
#define NV3 (NV*3)          // 42186
#define KD 120              // 63 pose-corr + 55 bsw + 2 zero pad (T excluded)
#define NTILE 96            // comps per block = 32 vertices exactly
#define VTILE 32
#define MTILE 64            // batches per M-tile iteration
#define NBLKS ((NV3 + NTILE - 1) / NTILE)   // 440
#define ST_PITCH 104        // staging row pitch in halves
#define DPITCH 14080        // dist row pitch (floats, 64-mult)
#define VPITCH 14080        // planar g_vert pitch

#define SB_WORDS (15*12*66)                  // 11880 (full-K B frags)
#define ST_BYTES (MTILE*ST_PITCH*2)          // 13312 (fp16 staging)
#define SMEM_BYTES (SB_WORDS*4 + ST_BYTES)   // 60832

// scratch (allocation-free requirement -> device globals)
__device__ __align__(16) uint32_t g_coefA[BATCH * KD];   // tf32 bits, A-frag order
__device__ __align__(16) float    g_bone[BATCH * NB * 12];
__device__ __align__(16) float    g_LT[256 * 256];       // transposed L
__device__ __align__(16) float    g_vertP[16 * VPITCH];  // planar per-vertex consts
__device__ __align__(16) float    g_dist[(size_t)BATCH * DPITCH]; // alpha*dist

struct Aff { float r[9]; float t[3]; };

__device__ __forceinline__ Aff amul(const Aff& A, const Aff& B) {
    Aff C;
#pragma unroll
    for (int i = 0; i < 3; i++) {
#pragma unroll
        for (int j = 0; j < 3; j++)
            C.r[i*3+j] = A.r[i*3+0]*B.r[0*3+j] + A.r[i*3+1]*B.r[1*3+j] + A.r[i*3+2]*B.r[2*3+j];
        C.t[i] = A.r[i*3+0]*B.t[0] + A.r[i*3+1]*B.t[1] + A.r[i*3+2]*B.t[2] + A.t[i];
    }
    return C;
}

__device__ __forceinline__ Aff ainv_rigid(const Aff& A) {
    Aff C;
#pragma unroll
    for (int i = 0; i < 3; i++)
#pragma unroll
        for (int j = 0; j < 3; j++)
            C.r[i*3+j] = A.r[j*3+i];
#pragma unroll
    for (int i = 0; i < 3; i++)
        C.t[i] = -(C.r[i*3+0]*A.t[0] + C.r[i*3+1]*A.t[1] + C.r[i*3+2]*A.t[2]);
    return C;
}

__device__ __forceinline__ void rodrigues(const float* rv, float* R) {
    float x = rv[0], y = rv[1], z = rv[2];
    float d = x*x + y*y + z*z + 1e-12f;
    float ang = sqrtf(d);
    float inv = 1.0f / ang;
    float kx = x*inv, ky = y*inv, kz = z*inv;
    float s = sinf(ang), c = cosf(ang);
    float kk = kx*kx + ky*ky + kz*kz;
    float oc = 1.0f - c;
    R[0] = 1.0f + oc*(kx*kx - kk);
    R[1] = -s*kz + oc*(kx*ky);
    R[2] =  s*ky + oc*(kx*kz);
    R[3] =  s*kz + oc*(ky*kx);
    R[4] = 1.0f + oc*(ky*ky - kk);
    R[5] = -s*kx + oc*(ky*kz);
    R[6] = -s*ky + oc*(kz*kx);
    R[7] =  s*kx + oc*(kz*ky);
    R[8] = 1.0f + oc*(kz*kz - kk);
}

__device__ __forceinline__ uint32_t to_tf32(float f) {
    uint32_t u;
    asm("cvt.rna.tf32.f32 %0, %1;" : "=r"(u) : "f"(f));
    return u;
}

// write coef value k for batch b into m16n8k8 A-fragment-ordered g_coefA
__device__ __forceinline__ void store_coef(int b, int k, float v) {
    int b64  = b >> 6;
    int mblk = (b >> 4) & 3;
    int r    = b & 15;
    int g    = r & 7;
    int hi   = r >> 3;
    int k8 = k >> 3, t = k & 7, tig = t & 3, j2 = t >> 2;
    int lane = g*4 + tig;
    int reg  = j2*2 + hi;
    g_coefA[(((b64*15 + k8)*4 + mblk)*32 + lane)*4 + reg] = to_tf32(v);
}

// Merged prep: one block per batch.
__global__ void prep_kernel(const float* __restrict__ theta,
                            const float* __restrict__ bsw,
                            const float* __restrict__ L2P) {
    __shared__ float sR[NB * 9];
    const int b = blockIdx.x;
    const int t = threadIdx.x;
    if (t < 8) {
        float R[9];
        rodrigues(theta + (b*NB + t)*3, R);
#pragma unroll
        for (int i = 0; i < 9; i++) sR[t*9 + i] = R[i];
        if (t >= 1) {
#pragma unroll
            for (int i = 0; i < 3; i++)
#pragma unroll
                for (int j = 0; j < 3; j++)
                    store_coef(b, (t-1)*9 + i*3 + j, R[i*3+j] - (i == j ? 1.0f : 0.0f));
        }
    } else if (t < 63) {
        int j = t - 8;
        store_coef(b, 63 + j, bsw[b*55 + j]);
    }
    __syncthreads();

    if (t == 0) {
        Aff M, rest;
#pragma unroll
        for (int n = 0; n < NB; n++) {
            Aff l2p;
#pragma unroll
            for (int i = 0; i < 3; i++) {
#pragma unroll
                for (int j = 0; j < 3; j++) l2p.r[i*3+j] = L2P[n*16 + i*4 + j];
                l2p.t[i] = L2P[n*16 + i*4 + 3];
            }
            Aff loc;
#pragma unroll
            for (int i = 0; i < 9; i++) loc.r[i] = sR[n*9 + i];
            loc.t[0] = loc.t[1] = loc.t[2] = 0.0f;

            Aff An = amul(l2p, loc);
            M    = (n == 0) ? An  : amul(M, An);
            rest = (n == 0) ? l2p : amul(rest, l2p);

            Aff w2l = ainv_rigid(rest);
            Aff G = amul(M, w2l);

            float* gp = g_bone + b*(NB*12) + n*12;
#pragma unroll
            for (int i = 0; i < 3; i++) {
                gp[i*4+0] = G.r[i*3+0];
                gp[i*4+1] = G.r[i*3+1];
                gp[i*4+2] = G.r[i*3+2];
                gp[i*4+3] = G.t[i];
            }
        }
    }
}

// transpose L (256x256): LT[x][y] = L[y][x].
__global__ void transpose_kernel(const float* __restrict__ L) {
    int y = blockIdx.x;
    int x = threadIdx.x;
    g_LT[x*256 + y] = L[y*256 + x];
}

// dist pass + planar per-vertex constant packing.
__global__ __launch_bounds__(256)
void dist_kernel(const float* __restrict__ uvgrid,
                 const float* __restrict__ tau,
                 const float* __restrict__ alpha,
                 const float* __restrict__ T,
                 const float* __restrict__ ts,
                 const float* __restrict__ W) {
    __shared__ float sd[8][32*33];
    const int tid  = threadIdx.x;
    const int w    = tid >> 5;
    const int lane = tid & 31;
    const int v0   = blockIdx.x * VTILE;

    // pack planar g_vertP[slot][v] for these 32 vertices
    for (int idx = tid; idx < 16*32; idx += 256) {
        int slot = idx >> 5, u = idx & 31;
        int v = v0 + u;
        if (v < NV) {
            float val = 0.0f;
            if (slot < 3)                    val = T[v*3 + slot];
            else if (slot >= 4 && slot < 7)  val = ts[v*3 + (slot-4)];
            else if (slot >= 8)              val = W[(slot-8)*NV + v];
            g_vertP[slot*VPITCH + v] = val;
        }
    }

    const int b  = w*32 + lane;
    const float tb = tau[b];
    const float al = alpha[b];
    float* sdw = sd[w];

    for (int u = 0; u < 32; u++) {
        int v = v0 + u;
        float val = 0.0f;
        if (v < NV) {
            float ux = uvgrid[v*2+0];
            float uy = uvgrid[v*2+1];
            float x = fminf(fmaxf(ux * 255.0f, 0.0f), 255.0f);
            int x0 = (int)floorf(x);
            int x1 = min(x0 + 1, 255);
            float wx = x - (float)x0;
            float y = fminf(fmaxf((uy + tb) * 255.0f, 0.0f), 255.0f);
            int y0 = (int)floorf(y);
            int y1 = min(y0 + 1, 255);
            float wy = y - (float)y0;
            float v00 = g_LT[x0*256 + y0], v01 = g_LT[x1*256 + y0];
            float v10 = g_LT[x0*256 + y1], v11 = g_LT[x1*256 + y1];
            val = al * ((v00*(1.0f-wx) + v01*wx)*(1.0f-wy)
                      + (v10*(1.0f-wx) + v11*wx)*wy);
        }
        sdw[u*33 + lane] = val;
    }
    __syncwarp();

#pragma unroll
    for (int j = 0; j < 8; j++) {
        int br = j*4 + (lane >> 3);
        int vc = (lane & 7) * 4;
        float4 val = make_float4(sdw[(vc+0)*33 + br], sdw[(vc+1)*33 + br],
                                 sdw[(vc+2)*33 + br], sdw[(vc+3)*33 + br]);
        *(float4*)&g_dist[(size_t)(w*32 + br)*DPITCH + v0 + vc] = val;
    }
}

// Fused tf32 GEMM + epilogue, B-stationary, 3 CTAs/SM, fp16 staging.
// Epilogue: lane = vertex, warp = 8 batch rows. g_bone loads are single-
// address (warp-uniform) LDG.128: 6 per row. State = 14 coalesced LDG.32
// from planar g_vertP, reloaded per M-tile after acc drain.
__global__ __launch_bounds__(256, 3)
void fused_kernel(const float* __restrict__ P,
                  const float* __restrict__ E,
                  float* __restrict__ out) {
    extern __shared__ __align__(16) char smem_raw[];
    uint32_t* sB = (uint32_t*)smem_raw;
    __half*   st = (__half*)(sB + SB_WORDS);

    const int tid   = threadIdx.x;
    const int lane  = tid & 31;
    const int wid   = tid >> 5;
    const int warpM = wid >> 2;      // 0..1
    const int warpN = wid & 3;       // 0..3
    const int cbase = blockIdx.x * NTILE;
    const int vbase = blockIdx.x * VTILE;

    // ---- fill full-K B tile [120 x 96] in fragment order (once) ----
    for (int idx = tid; idx < KD*NTILE; idx += 256) {
        int kl = idx / NTILE;
        int cl = idx - kl*NTILE;
        int c  = cbase + cl;
        float v = 0.0f;
        if (c < NV3) {
            if (kl < 63)       v = P[(size_t)(kl+9)*NV3 + c];
            else if (kl < 118) v = E[(size_t)(kl-63)*NV3 + c];
        }
        int k8 = kl >> 3, t = kl & 7, tig = t & 3, j = t >> 2;
        int nblk = cl >> 3, gg = cl & 7;
        sB[k8*(12*66) + nblk*66 + (gg*4 + tig)*2 + j] = to_tf32(v);
    }

    const int v = vbase + lane;          // this lane's vertex
    const bool lval = (v < NV);

    __syncthreads();

    // ---- M-tile loop ----
    for (int mt = 0; mt < 4; mt++) {
        const uint32_t* Ag = g_coefA + mt*(MTILE*KD);
        const int Mbase = mt * MTILE;

        float acc[2][3][4];
#pragma unroll
        for (int mi = 0; mi < 2; mi++)
#pragma unroll
            for (int ni = 0; ni < 3; ni++)
#pragma unroll
                for (int qq = 0; qq < 4; qq++) acc[mi][ni][qq] = 0.0f;

#pragma unroll
        for (int k8 = 0; k8 < 15; k8++) {
            uint32_t a[2][4];
#pragma unroll
            for (int mi = 0; mi < 2; mi++) {
                uint4 av = *(const uint4*)&Ag[((k8*4 + warpM*2 + mi)*32 + lane)*4];
                a[mi][0] = av.x; a[mi][1] = av.y; a[mi][2] = av.z; a[mi][3] = av.w;
            }
            uint32_t bf[3][2];
#pragma unroll
            for (int ni = 0; ni < 3; ni++) {
                uint2 bv = *(const uint2*)&sB[k8*(12*66) + (warpN*3 + ni)*66 + lane*2];
                bf[ni][0] = bv.x; bf[ni][1] = bv.y;
            }
#pragma unroll
            for (int mi = 0; mi < 2; mi++)
#pragma unroll
                for (int ni = 0; ni < 3; ni++) {
                    asm volatile(
                        "mma.sync.aligned.m16n8k8.row.col.f32.tf32.tf32.f32 "
                        "{%0,%1,%2,%3}, {%4,%5,%6,%7}, {%8,%9}, {%0,%1,%2,%3};"
                        : "+f"(acc[mi][ni][0]), "+f"(acc[mi][ni][1]),
                          "+f"(acc[mi][ni][2]), "+f"(acc[mi][ni][3])
                        : "r"(a[mi][0]), "r"(a[mi][1]), "r"(a[mi][2]), "r"(a[mi][3]),
                          "r"(bf[ni][0]), "r"(bf[ni][1]));
                }
        }

        __syncthreads();   // previous epilogue done reading staging
        {
            const int gg  = lane >> 2;
            const int tt4 = lane & 3;
#pragma unroll
            for (int mi = 0; mi < 2; mi++) {
#pragma unroll
                for (int ni = 0; ni < 3; ni++) {
                    int row = warpM*32 + mi*16 + gg;
                    int col = warpN*24 + ni*8 + tt4*2;
                    *(__half2*)&st[row*ST_PITCH + col] =
                        __floats2half2_rn(acc[mi][ni][0], acc[mi][ni][1]);
                    *(__half2*)&st[(row+8)*ST_PITCH + col] =
                        __floats2half2_rn(acc[mi][ni][2], acc[mi][ni][3]);
                }
            }
        }
        __syncthreads();

        if (lval) {
            // planar per-vertex state: 14 coalesced LDG.32
            float T0  = g_vertP[ 0*VPITCH + v];
            float T1  = g_vertP[ 1*VPITCH + v];
            float T2  = g_vertP[ 2*VPITCH + v];
            float ts0 = g_vertP[ 4*VPITCH + v];
            float ts1 = g_vertP[ 5*VPITCH + v];
            float ts2 = g_vertP[ 6*VPITCH + v];
            float w8[NB];
#pragma unroll
            for (int n = 0; n < NB; n++) w8[n] = g_vertP[(8+n)*VPITCH + v];

            // epilogue: 8 rows, G warp-uniform per row
#pragma unroll
            for (int rr = 0; rr < 8; rr++) {
                const int row = wid*8 + rr;
                const int b = Mbase + row;

                float s = g_dist[(size_t)b*DPITCH + v];   // coalesced

                float cx = __half2float(st[row*ST_PITCH + lane*3 + 0]);
                float cy = __half2float(st[row*ST_PITCH + lane*3 + 1]);
                float cz = __half2float(st[row*ST_PITCH + lane*3 + 2]);

                float px = cx + T0 + s*ts0;
                float py = cy + T1 + s*ts1;
                float pz = cz + T2 + s*ts2;

                const float4* Gb = (const float4*)(g_bone + b*(NB*12));
                float ox = 0.0f, oy = 0.0f, oz = 0.0f;
#pragma unroll
                for (int n = 0; n < NB; n++) {
                    float4 g0 = Gb[n*3 + 0];   // single-address across warp
                    float4 g1 = Gb[n*3 + 1];
                    float4 g2 = Gb[n*3 + 2];
                    float wn = w8[n];
                    ox = fmaf(wn, fmaf(g0.x, px, fmaf(g0.y, py, fmaf(g0.z, pz, g0.w))), ox);
                    oy = fmaf(wn, fmaf(g1.x, px, fmaf(g1.y, py, fmaf(g1.z, pz, g1.w))), oy);
                    oz = fmaf(wn, fmaf(g2.x, px, fmaf(g2.y, py, fmaf(g2.z, pz, g2.w))), oz);
                }

                size_t base = (size_t)b * NV3 + (size_t)v * 3;
                out[base + 0] = ox;     // coalesced across warp
                out[base + 1] = oy;
                out[base + 2] = oz;
            }
        }
    }
}

extern "C" void kernel_launch(void* const* d_in, const int* in_sizes, int n_in,
                              void* d_out, int out_size) {
    const float* theta  = (const float*)d_in[0];
    const float* tau    = (const float*)d_in[1];
    const float* alpha  = (const float*)d_in[2];
    const float* bsw    = (const float*)d_in[3];
    const float* W      = (const float*)d_in[4];
    const float* T      = (const float*)d_in[5];
    const float* P      = (const float*)d_in[6];
    const float* L      = (const float*)d_in[7];
    const float* ts     = (const float*)d_in[8];
    const float* L2P    = (const float*)d_in[9];
    const float* E      = (const float*)d_in[10];
    const float* uvgrid = (const float*)d_in[11];
    float* out = (float*)d_out;

    cudaFuncSetAttribute(fused_kernel,
                         cudaFuncAttributeMaxDynamicSharedMemorySize, SMEM_BYTES);

    prep_kernel<<<BATCH, 64>>>(theta, bsw, L2P);
    transpose_kernel<<<256, 256>>>(L);
    dist_kernel<<<NBLKS, 256>>>(uvgrid, tau, alpha, T, ts, W);

    fused_kernel<<<NBLKS, 256, SMEM_BYTES>>>(P, E, out);
}

// round 15
// speedup vs baseline: 1.1075x; 1.1075x over previous
#include <cuda_runtime.h>
#include <cuda_bf16.h>
#include <cuda_fp16.h>
#include <math.h>
#include <stdint.h>

#define NB 8
#define BATCH 256
#define NV 14062
#define NV3 (NV*3)          // 42186
#define KD 120              // 63 pose-corr + 55 bsw + 2 zero pad (T excluded)
#define NTILE 96            // comps per block = 32 vertices exactly
#define VTILE 32
#define MTILE 64            // batches per M-tile iteration
#define NBLKS ((NV3 + NTILE - 1) / NTILE)   // 440
#define ST_PITCH 104        // staging row pitch in halves
#define DPITCH 14080        // dist row pitch (floats, 64-mult)

#define SB_WORDS (15*12*66)                   // 11880 (full-K B frags)
#define ST_HALVES (MTILE*ST_PITCH)            // 6656 halves per buffer
#define SMEM_BYTES (SB_WORDS*4 + 2*ST_HALVES*2)   // 74144 (3 CTAs = 217KB)

// scratch (allocation-free requirement -> device globals)
__device__ __align__(16) uint32_t g_coefA[BATCH * KD];   // tf32 bits, A-frag order
__device__ __align__(16) float    g_bone[BATCH * NB * 12];
__device__ __align__(16) float    g_LT[256 * 256];       // transposed L
__device__ __align__(16) float    g_vert[14080 * 16];    // packed per-vertex consts
__device__ __align__(16) float    g_dist[(size_t)BATCH * DPITCH]; // alpha*dist

struct Aff { float r[9]; float t[3]; };

__device__ __forceinline__ Aff amul(const Aff& A, const Aff& B) {
    Aff C;
#pragma unroll
    for (int i = 0; i < 3; i++) {
#pragma unroll
        for (int j = 0; j < 3; j++)
            C.r[i*3+j] = A.r[i*3+0]*B.r[0*3+j] + A.r[i*3+1]*B.r[1*3+j] + A.r[i*3+2]*B.r[2*3+j];
        C.t[i] = A.r[i*3+0]*B.t[0] + A.r[i*3+1]*B.t[1] + A.r[i*3+2]*B.t[2] + A.t[i];
    }
    return C;
}

__device__ __forceinline__ Aff ainv_rigid(const Aff& A) {
    Aff C;
#pragma unroll
    for (int i = 0; i < 3; i++)
#pragma unroll
        for (int j = 0; j < 3; j++)
            C.r[i*3+j] = A.r[j*3+i];
#pragma unroll
    for (int i = 0; i < 3; i++)
        C.t[i] = -(C.r[i*3+0]*A.t[0] + C.r[i*3+1]*A.t[1] + C.r[i*3+2]*A.t[2]);
    return C;
}

__device__ __forceinline__ void rodrigues(const float* rv, float* R) {
    float x = rv[0], y = rv[1], z = rv[2];
    float d = x*x + y*y + z*z + 1e-12f;
    float ang = sqrtf(d);
    float inv = 1.0f / ang;
    float kx = x*inv, ky = y*inv, kz = z*inv;
    float s = sinf(ang), c = cosf(ang);
    float kk = kx*kx + ky*ky + kz*kz;
    float oc = 1.0f - c;
    R[0] = 1.0f + oc*(kx*kx - kk);
    R[1] = -s*kz + oc*(kx*ky);
    R[2] =  s*ky + oc*(kx*kz);
    R[3] =  s*kz + oc*(ky*kx);
    R[4] = 1.0f + oc*(ky*ky - kk);
    R[5] = -s*kx + oc*(ky*kz);
    R[6] = -s*ky + oc*(kz*kx);
    R[7] =  s*kx + oc*(kz*ky);
    R[8] = 1.0f + oc*(kz*kz - kk);
}

__device__ __forceinline__ uint32_t to_tf32(float f) {
    uint32_t u;
    asm("cvt.rna.tf32.f32 %0, %1;" : "=r"(u) : "f"(f));
    return u;
}

// write coef value k for batch b into m16n8k8 A-fragment-ordered g_coefA
__device__ __forceinline__ void store_coef(int b, int k, float v) {
    int b64  = b >> 6;
    int mblk = (b >> 4) & 3;
    int r    = b & 15;
    int g    = r & 7;
    int hi   = r >> 3;
    int k8 = k >> 3, t = k & 7, tig = t & 3, j2 = t >> 2;
    int lane = g*4 + tig;
    int reg  = j2*2 + hi;
    g_coefA[(((b64*15 + k8)*4 + mblk)*32 + lane)*4 + reg] = to_tf32(v);
}

// B-fragment smem offset for (k-row kl, comp col cl)
__device__ __forceinline__ int bfrag_off(int kl, int cl) {
    int k8 = kl >> 3, t = kl & 7, tig = t & 3, j = t >> 2;
    int nblk = cl >> 3, gg = cl & 7;
    return k8*(12*66) + nblk*66 + (gg*4 + tig)*2 + j;
}

// Merged prep: one block per batch.
__global__ void prep_kernel(const float* __restrict__ theta,
                            const float* __restrict__ bsw,
                            const float* __restrict__ L2P) {
    __shared__ float sR[NB * 9];
    const int b = blockIdx.x;
    const int t = threadIdx.x;
    if (t < 8) {
        float R[9];
        rodrigues(theta + (b*NB + t)*3, R);
#pragma unroll
        for (int i = 0; i < 9; i++) sR[t*9 + i] = R[i];
        if (t >= 1) {
#pragma unroll
            for (int i = 0; i < 3; i++)
#pragma unroll
                for (int j = 0; j < 3; j++)
                    store_coef(b, (t-1)*9 + i*3 + j, R[i*3+j] - (i == j ? 1.0f : 0.0f));
        }
    } else if (t < 63) {
        int j = t - 8;
        store_coef(b, 63 + j, bsw[b*55 + j]);
    }
    __syncthreads();

    if (t == 0) {
        Aff M, rest;
#pragma unroll
        for (int n = 0; n < NB; n++) {
            Aff l2p;
#pragma unroll
            for (int i = 0; i < 3; i++) {
#pragma unroll
                for (int j = 0; j < 3; j++) l2p.r[i*3+j] = L2P[n*16 + i*4 + j];
                l2p.t[i] = L2P[n*16 + i*4 + 3];
            }
            Aff loc;
#pragma unroll
            for (int i = 0; i < 9; i++) loc.r[i] = sR[n*9 + i];
            loc.t[0] = loc.t[1] = loc.t[2] = 0.0f;

            Aff An = amul(l2p, loc);
            M    = (n == 0) ? An  : amul(M, An);
            rest = (n == 0) ? l2p : amul(rest, l2p);

            Aff w2l = ainv_rigid(rest);
            Aff G = amul(M, w2l);

            float* gp = g_bone + b*(NB*12) + n*12;
#pragma unroll
            for (int i = 0; i < 3; i++) {
                gp[i*4+0] = G.r[i*3+0];
                gp[i*4+1] = G.r[i*3+1];
                gp[i*4+2] = G.r[i*3+2];
                gp[i*4+3] = G.t[i];
            }
        }
    }
}

// transpose L (256x256): LT[x][y] = L[y][x].
__global__ void transpose_kernel(const float* __restrict__ L) {
    int y = blockIdx.x;
    int x = threadIdx.x;
    g_LT[x*256 + y] = L[y*256 + x];
}

// dist pass + packed per-vertex constants.
__global__ __launch_bounds__(256)
void dist_kernel(const float* __restrict__ uvgrid,
                 const float* __restrict__ tau,
                 const float* __restrict__ alpha,
                 const float* __restrict__ T,
                 const float* __restrict__ ts,
                 const float* __restrict__ W) {
    __shared__ float sd[8][32*33];
    const int tid  = threadIdx.x;
    const int w    = tid >> 5;
    const int lane = tid & 31;
    const int v0   = blockIdx.x * VTILE;

    for (int idx = tid; idx < 32*16; idx += 256) {
        int u = idx >> 4, slot = idx & 15;
        int v = v0 + u;
        if (v < NV) {
            float val = 0.0f;
            if (slot < 3)                    val = T[v*3 + slot];
            else if (slot >= 4 && slot < 7)  val = ts[v*3 + (slot-4)];
            else if (slot >= 8)              val = W[(slot-8)*NV + v];
            g_vert[v*16 + slot] = val;
        }
    }

    const int b  = w*32 + lane;
    const float tb = tau[b];
    const float al = alpha[b];
    float* sdw = sd[w];

    for (int u = 0; u < 32; u++) {
        int v = v0 + u;
        float val = 0.0f;
        if (v < NV) {
            float ux = uvgrid[v*2+0];
            float uy = uvgrid[v*2+1];
            float x = fminf(fmaxf(ux * 255.0f, 0.0f), 255.0f);
            int x0 = (int)floorf(x);
            int x1 = min(x0 + 1, 255);
            float wx = x - (float)x0;
            float y = fminf(fmaxf((uy + tb) * 255.0f, 0.0f), 255.0f);
            int y0 = (int)floorf(y);
            int y1 = min(y0 + 1, 255);
            float wy = y - (float)y0;
            float v00 = g_LT[x0*256 + y0], v01 = g_LT[x1*256 + y0];
            float v10 = g_LT[x0*256 + y1], v11 = g_LT[x1*256 + y1];
            val = al * ((v00*(1.0f-wx) + v01*wx)*(1.0f-wy)
                      + (v10*(1.0f-wx) + v11*wx)*wy);
        }
        sdw[u*33 + lane] = val;
    }
    __syncwarp();

#pragma unroll
    for (int j = 0; j < 8; j++) {
        int br = j*4 + (lane >> 3);
        int vc = (lane & 7) * 4;
        float4 val = make_float4(sdw[(vc+0)*33 + br], sdw[(vc+1)*33 + br],
                                 sdw[(vc+2)*33 + br], sdw[(vc+3)*33 + br]);
        *(float4*)&g_dist[(size_t)(w*32 + br)*DPITCH + v0 + vc] = val;
    }
}

// Fused tf32 GEMM + epilogue, B-stationary, 3 CTAs/SM, DOUBLE-BUFFERED fp16
// staging (one barrier per M-tile; epilogue of tile mt overlaps MMA of mt+1
// across warps). B-fill vectorized with float2 (NV3 is even).
__global__ __launch_bounds__(256, 3)
void fused_kernel(const float* __restrict__ P,
                  const float* __restrict__ E,
                  float* __restrict__ out) {
    extern __shared__ __align__(16) char smem_raw[];
    uint32_t* sB = (uint32_t*)smem_raw;
    __half*   st0 = (__half*)(sB + SB_WORDS);

    const int tid   = threadIdx.x;
    const int lane  = tid & 31;
    const int wid   = tid >> 5;
    const int warpM = wid >> 2;      // 0..1
    const int warpN = wid & 3;       // 0..3
    const int cbase = blockIdx.x * NTILE;
    const int vbase = blockIdx.x * VTILE;

    // ---- fill full-K B tile [120 x 96] in fragment order (once) ----
    if (cbase + NTILE <= NV3) {
        // vectorized: float2 loads (rows are 2-element aligned)
        for (int idx = tid; idx < KD*(NTILE/2); idx += 256) {
            int kl = idx / (NTILE/2);
            int c2 = idx - kl*(NTILE/2);
            int cl = c2*2;
            float2 v2 = make_float2(0.0f, 0.0f);
            if (kl < 63)
                v2 = *(const float2*)&P[(size_t)(kl+9)*NV3 + cbase + cl];
            else if (kl < 118)
                v2 = *(const float2*)&E[(size_t)(kl-63)*NV3 + cbase + cl];
            sB[bfrag_off(kl, cl)]     = to_tf32(v2.x);
            sB[bfrag_off(kl, cl + 1)] = to_tf32(v2.y);
        }
    } else {
        // tail block: scalar with bounds guard
        for (int idx = tid; idx < KD*NTILE; idx += 256) {
            int kl = idx / NTILE;
            int cl = idx - kl*NTILE;
            int c  = cbase + cl;
            float v = 0.0f;
            if (c < NV3) {
                if (kl < 63)       v = P[(size_t)(kl+9)*NV3 + c];
                else if (kl < 118) v = E[(size_t)(kl-63)*NV3 + c];
            }
            sB[bfrag_off(kl, cl)] = to_tf32(v);
        }
    }

    // epilogue thread mapping: 2 adjacent vertices x 4 rows
    const int vl2  = tid & 15;
    const int rgrp = tid >> 4;
    const int vp   = vbase + vl2*2;
    const bool valid = (vp < NV);

    __syncthreads();

    // ---- M-tile loop ----
    for (int mt = 0; mt < 4; mt++) {
        const uint32_t* Ag = g_coefA + mt*(MTILE*KD);
        const int Mbase = mt * MTILE;
        __half* st = st0 + (mt & 1) * ST_HALVES;

        float acc[2][3][4];
#pragma unroll
        for (int mi = 0; mi < 2; mi++)
#pragma unroll
            for (int ni = 0; ni < 3; ni++)
#pragma unroll
                for (int qq = 0; qq < 4; qq++) acc[mi][ni][qq] = 0.0f;

#pragma unroll
        for (int k8 = 0; k8 < 15; k8++) {
            uint32_t a[2][4];
#pragma unroll
            for (int mi = 0; mi < 2; mi++) {
                uint4 av = *(const uint4*)&Ag[((k8*4 + warpM*2 + mi)*32 + lane)*4];
                a[mi][0] = av.x; a[mi][1] = av.y; a[mi][2] = av.z; a[mi][3] = av.w;
            }
            uint32_t bf[3][2];
#pragma unroll
            for (int ni = 0; ni < 3; ni++) {
                uint2 bv = *(const uint2*)&sB[k8*(12*66) + (warpN*3 + ni)*66 + lane*2];
                bf[ni][0] = bv.x; bf[ni][1] = bv.y;
            }
#pragma unroll
            for (int mi = 0; mi < 2; mi++)
#pragma unroll
                for (int ni = 0; ni < 3; ni++) {
                    asm volatile(
                        "mma.sync.aligned.m16n8k8.row.col.f32.tf32.tf32.f32 "
                        "{%0,%1,%2,%3}, {%4,%5,%6,%7}, {%8,%9}, {%0,%1,%2,%3};"
                        : "+f"(acc[mi][ni][0]), "+f"(acc[mi][ni][1]),
                          "+f"(acc[mi][ni][2]), "+f"(acc[mi][ni][3])
                        : "r"(a[mi][0]), "r"(a[mi][1]), "r"(a[mi][2]), "r"(a[mi][3]),
                          "r"(bf[ni][0]), "r"(bf[ni][1]));
                }
        }

        // drain accumulators into this tile's staging buffer (no pre-sync:
        // other buffer is the one previous epilogue reads)
        {
            const int gg  = lane >> 2;
            const int tt4 = lane & 3;
#pragma unroll
            for (int mi = 0; mi < 2; mi++) {
#pragma unroll
                for (int ni = 0; ni < 3; ni++) {
                    int row = warpM*32 + mi*16 + gg;
                    int col = warpN*24 + ni*8 + tt4*2;
                    *(__half2*)&st[row*ST_PITCH + col] =
                        __floats2half2_rn(acc[mi][ni][0], acc[mi][ni][1]);
                    *(__half2*)&st[(row+8)*ST_PITCH + col] =
                        __floats2half2_rn(acc[mi][ni][2], acc[mi][ni][3]);
                }
            }
        }
        __syncthreads();   // publish staging for this tile

        if (valid) {
            // packed per-vertex state: 4 LDG.128 per vertex (L1-hot for mt>0)
            float hT[2][3], hts[2][3], hw8[2][NB];
#pragma unroll
            for (int u = 0; u < 2; u++) {
                const float4* gv = (const float4*)&g_vert[(vp+u)*16];
                float4 a0 = gv[0], a1 = gv[1], a2 = gv[2], a3 = gv[3];
                hT[u][0] = a0.x; hT[u][1] = a0.y; hT[u][2] = a0.z;
                hts[u][0] = a1.x; hts[u][1] = a1.y; hts[u][2] = a1.z;
                hw8[u][0] = a2.x; hw8[u][1] = a2.y; hw8[u][2] = a2.z; hw8[u][3] = a2.w;
                hw8[u][4] = a3.x; hw8[u][5] = a3.y; hw8[u][6] = a3.z; hw8[u][7] = a3.w;
            }

            // epilogue: 4 rows x 2 vertices per thread
#pragma unroll
            for (int i = 0; i < 4; i++) {
                const int row = rgrp + i*16;
                const int b = Mbase + row;

                float2 dv = *(const float2*)&g_dist[(size_t)b*DPITCH + vp];

                const __half* sp = st + row*ST_PITCH + vl2*6;
                float2 f0 = __half22float2(*(const __half2*)(sp + 0));
                float2 f1 = __half22float2(*(const __half2*)(sp + 2));
                float2 f2 = __half22float2(*(const __half2*)(sp + 4));
                float cc[6] = {f0.x, f0.y, f1.x, f1.y, f2.x, f2.y};

                float px[2], py[2], pz[2], ox[2], oy[2], oz[2];
#pragma unroll
                for (int u = 0; u < 2; u++) {
                    float s = (u == 0) ? dv.x : dv.y;
                    px[u] = cc[u*3+0] + hT[u][0] + s*hts[u][0];
                    py[u] = cc[u*3+1] + hT[u][1] + s*hts[u][1];
                    pz[u] = cc[u*3+2] + hT[u][2] + s*hts[u][2];
                    ox[u] = 0.0f; oy[u] = 0.0f; oz[u] = 0.0f;
                }

                const float4* Gb = (const float4*)(g_bone + b*(NB*12));
#pragma unroll
                for (int n = 0; n < NB; n++) {
                    float4 g0 = Gb[n*3 + 0];
                    float4 g1 = Gb[n*3 + 1];
                    float4 g2 = Gb[n*3 + 2];
#pragma unroll
                    for (int u = 0; u < 2; u++) {
                        float wn = hw8[u][n];
                        ox[u] = fmaf(wn, fmaf(g0.x, px[u], fmaf(g0.y, py[u], fmaf(g0.z, pz[u], g0.w))), ox[u]);
                        oy[u] = fmaf(wn, fmaf(g1.x, px[u], fmaf(g1.y, py[u], fmaf(g1.z, pz[u], g1.w))), oy[u]);
                        oz[u] = fmaf(wn, fmaf(g2.x, px[u], fmaf(g2.y, py[u], fmaf(g2.z, pz[u], g2.w))), oz[u]);
                    }
                }

                size_t base = (size_t)b * NV3 + (size_t)vp * 3;   // even offset
                *(float2*)&out[base + 0] = make_float2(ox[0], oy[0]);
                *(float2*)&out[base + 2] = make_float2(oz[0], ox[1]);
                *(float2*)&out[base + 4] = make_float2(oy[1], oz[1]);
            }
        }
        // no trailing barrier: next drain targets the other staging buffer
    }
}

extern "C" void kernel_launch(void* const* d_in, const int* in_sizes, int n_in,
                              void* d_out, int out_size) {
    const float* theta  = (const float*)d_in[0];
    const float* tau    = (const float*)d_in[1];
    const float* alpha  = (const float*)d_in[2];
    const float* bsw    = (const float*)d_in[3];
    const float* W      = (const float*)d_in[4];
    const float* T      = (const float*)d_in[5];
    const float* P      = (const float*)d_in[6];
    const float* L      = (const float*)d_in[7];
    const float* ts     = (const float*)d_in[8];
    const float* L2P    = (const float*)d_in[9];
    const float* E      = (const float*)d_in[10];
    const float* uvgrid = (const float*)d_in[11];
    float* out = (float*)d_out;

    cudaFuncSetAttribute(fused_kernel,
                         cudaFuncAttributeMaxDynamicSharedMemorySize, SMEM_BYTES);

    prep_kernel<<<BATCH, 64>>>(theta, bsw, L2P);
    transpose_kernel<<<256, 256>>>(L);
    dist_kernel<<<NBLKS, 256>>>(uvgrid, tau, alpha, T, ts, W);

    fused_kernel<<<NBLKS, 256, SMEM_BYTES>>>(P, E, out);
}

// round 16
// speedup vs baseline: 1.2125x; 1.0948x over previous
#include <cuda_runtime.h>
#include <cuda_bf16.h>
#include <cuda_fp16.h>
#include <math.h>
#include <stdint.h>

#define NB 8
#define BATCH 256
#define NV 14062
#define NV3 (NV*3)          // 42186
#define KD 120              // 63 pose-corr + 55 bsw + 2 zero pad (T excluded)
#define NTILE 96            // comps per block = 32 vertices exactly
#define VTILE 32
#define MTILE 64            // batches per M-tile iteration
#define NBLKS ((NV3 + NTILE - 1) / NTILE)   // 440
#define ST_PITCH 104        // staging row pitch in halves
#define DPITCH 14080        // dist row pitch (floats, 64-mult)

#define SB_WORDS (15*12*66)                   // 11880 (full-K B frags)
#define ST_HALVES (MTILE*ST_PITCH)            // 6656 halves per buffer
#define SMEM_BYTES (SB_WORDS*4 + 2*ST_HALVES*2)   // 74144 (3 CTAs = 217KB)

// scratch (allocation-free requirement -> device globals)
__device__ __align__(16) uint32_t g_coefA[BATCH * KD];   // tf32 bits, A-frag order
__device__ __align__(16) __half   g_boneH[BATCH * NB * 12]; // fp16 bone mats
__device__ __align__(16) float    g_LT[256 * 256];       // transposed L
__device__ __align__(16) float    g_vert[14080 * 16];    // packed per-vertex consts
__device__ __align__(16) float    g_dist[(size_t)BATCH * DPITCH]; // alpha*dist

struct Aff { float r[9]; float t[3]; };

__device__ __forceinline__ Aff amul(const Aff& A, const Aff& B) {
    Aff C;
#pragma unroll
    for (int i = 0; i < 3; i++) {
#pragma unroll
        for (int j = 0; j < 3; j++)
            C.r[i*3+j] = A.r[i*3+0]*B.r[0*3+j] + A.r[i*3+1]*B.r[1*3+j] + A.r[i*3+2]*B.r[2*3+j];
        C.t[i] = A.r[i*3+0]*B.t[0] + A.r[i*3+1]*B.t[1] + A.r[i*3+2]*B.t[2] + A.t[i];
    }
    return C;
}

__device__ __forceinline__ Aff ainv_rigid(const Aff& A) {
    Aff C;
#pragma unroll
    for (int i = 0; i < 3; i++)
#pragma unroll
        for (int j = 0; j < 3; j++)
            C.r[i*3+j] = A.r[j*3+i];
#pragma unroll
    for (int i = 0; i < 3; i++)
        C.t[i] = -(C.r[i*3+0]*A.t[0] + C.r[i*3+1]*A.t[1] + C.r[i*3+2]*A.t[2]);
    return C;
}

__device__ __forceinline__ void rodrigues(const float* rv, float* R) {
    float x = rv[0], y = rv[1], z = rv[2];
    float d = x*x + y*y + z*z + 1e-12f;
    float ang = sqrtf(d);
    float inv = 1.0f / ang;
    float kx = x*inv, ky = y*inv, kz = z*inv;
    float s = sinf(ang), c = cosf(ang);
    float kk = kx*kx + ky*ky + kz*kz;
    float oc = 1.0f - c;
    R[0] = 1.0f + oc*(kx*kx - kk);
    R[1] = -s*kz + oc*(kx*ky);
    R[2] =  s*ky + oc*(kx*kz);
    R[3] =  s*kz + oc*(ky*kx);
    R[4] = 1.0f + oc*(ky*ky - kk);
    R[5] = -s*kx + oc*(ky*kz);
    R[6] = -s*ky + oc*(kz*kx);
    R[7] =  s*kx + oc*(kz*ky);
    R[8] = 1.0f + oc*(kz*kz - kk);
}

__device__ __forceinline__ uint32_t to_tf32(float f) {
    uint32_t u;
    asm("cvt.rna.tf32.f32 %0, %1;" : "=r"(u) : "f"(f));
    return u;
}

// write coef value k for batch b into m16n8k8 A-fragment-ordered g_coefA
__device__ __forceinline__ void store_coef(int b, int k, float v) {
    int b64  = b >> 6;
    int mblk = (b >> 4) & 3;
    int r    = b & 15;
    int g    = r & 7;
    int hi   = r >> 3;
    int k8 = k >> 3, t = k & 7, tig = t & 3, j2 = t >> 2;
    int lane = g*4 + tig;
    int reg  = j2*2 + hi;
    g_coefA[(((b64*15 + k8)*4 + mblk)*32 + lane)*4 + reg] = to_tf32(v);
}

// B-fragment smem offset for (k-row kl, comp col cl)
__device__ __forceinline__ int bfrag_off(int kl, int cl) {
    int k8 = kl >> 3, t = kl & 7, tig = t & 3, j = t >> 2;
    int nblk = cl >> 3, gg = cl & 7;
    return k8*(12*66) + nblk*66 + (gg*4 + tig)*2 + j;
}

// Merged prep: one block per batch.
__global__ void prep_kernel(const float* __restrict__ theta,
                            const float* __restrict__ bsw,
                            const float* __restrict__ L2P) {
    __shared__ float sR[NB * 9];
    const int b = blockIdx.x;
    const int t = threadIdx.x;
    if (t < 8) {
        float R[9];
        rodrigues(theta + (b*NB + t)*3, R);
#pragma unroll
        for (int i = 0; i < 9; i++) sR[t*9 + i] = R[i];
        if (t >= 1) {
#pragma unroll
            for (int i = 0; i < 3; i++)
#pragma unroll
                for (int j = 0; j < 3; j++)
                    store_coef(b, (t-1)*9 + i*3 + j, R[i*3+j] - (i == j ? 1.0f : 0.0f));
        }
    } else if (t < 63) {
        int j = t - 8;
        store_coef(b, 63 + j, bsw[b*55 + j]);
    }
    __syncthreads();

    if (t == 0) {
        Aff M, rest;
#pragma unroll
        for (int n = 0; n < NB; n++) {
            Aff l2p;
#pragma unroll
            for (int i = 0; i < 3; i++) {
#pragma unroll
                for (int j = 0; j < 3; j++) l2p.r[i*3+j] = L2P[n*16 + i*4 + j];
                l2p.t[i] = L2P[n*16 + i*4 + 3];
            }
            Aff loc;
#pragma unroll
            for (int i = 0; i < 9; i++) loc.r[i] = sR[n*9 + i];
            loc.t[0] = loc.t[1] = loc.t[2] = 0.0f;

            Aff An = amul(l2p, loc);
            M    = (n == 0) ? An  : amul(M, An);
            rest = (n == 0) ? l2p : amul(rest, l2p);

            Aff w2l = ainv_rigid(rest);
            Aff G = amul(M, w2l);

            __half* gp = g_boneH + b*(NB*12) + n*12;
#pragma unroll
            for (int i = 0; i < 3; i++) {
                gp[i*4+0] = __float2half_rn(G.r[i*3+0]);
                gp[i*4+1] = __float2half_rn(G.r[i*3+1]);
                gp[i*4+2] = __float2half_rn(G.r[i*3+2]);
                gp[i*4+3] = __float2half_rn(G.t[i]);
            }
        }
    }
}

// transpose L (256x256): LT[x][y] = L[y][x].
__global__ void transpose_kernel(const float* __restrict__ L) {
    int y = blockIdx.x;
    int x = threadIdx.x;
    g_LT[x*256 + y] = L[y*256 + x];
}

// dist pass + packed per-vertex constants.
__global__ __launch_bounds__(256)
void dist_kernel(const float* __restrict__ uvgrid,
                 const float* __restrict__ tau,
                 const float* __restrict__ alpha,
                 const float* __restrict__ T,
                 const float* __restrict__ ts,
                 const float* __restrict__ W) {
    __shared__ float sd[8][32*33];
    const int tid  = threadIdx.x;
    const int w    = tid >> 5;
    const int lane = tid & 31;
    const int v0   = blockIdx.x * VTILE;

    for (int idx = tid; idx < 32*16; idx += 256) {
        int u = idx >> 4, slot = idx & 15;
        int v = v0 + u;
        if (v < NV) {
            float val = 0.0f;
            if (slot < 3)                    val = T[v*3 + slot];
            else if (slot >= 4 && slot < 7)  val = ts[v*3 + (slot-4)];
            else if (slot >= 8)              val = W[(slot-8)*NV + v];
            g_vert[v*16 + slot] = val;
        }
    }

    const int b  = w*32 + lane;
    const float tb = tau[b];
    const float al = alpha[b];
    float* sdw = sd[w];

    for (int u = 0; u < 32; u++) {
        int v = v0 + u;
        float val = 0.0f;
        if (v < NV) {
            float ux = uvgrid[v*2+0];
            float uy = uvgrid[v*2+1];
            float x = fminf(fmaxf(ux * 255.0f, 0.0f), 255.0f);
            int x0 = (int)floorf(x);
            int x1 = min(x0 + 1, 255);
            float wx = x - (float)x0;
            float y = fminf(fmaxf((uy + tb) * 255.0f, 0.0f), 255.0f);
            int y0 = (int)floorf(y);
            int y1 = min(y0 + 1, 255);
            float wy = y - (float)y0;
            float v00 = g_LT[x0*256 + y0], v01 = g_LT[x1*256 + y0];
            float v10 = g_LT[x0*256 + y1], v11 = g_LT[x1*256 + y1];
            val = al * ((v00*(1.0f-wx) + v01*wx)*(1.0f-wy)
                      + (v10*(1.0f-wx) + v11*wx)*wy);
        }
        sdw[u*33 + lane] = val;
    }
    __syncwarp();

#pragma unroll
    for (int j = 0; j < 8; j++) {
        int br = j*4 + (lane >> 3);
        int vc = (lane & 7) * 4;
        float4 val = make_float4(sdw[(vc+0)*33 + br], sdw[(vc+1)*33 + br],
                                 sdw[(vc+2)*33 + br], sdw[(vc+3)*33 + br]);
        *(float4*)&g_dist[(size_t)(w*32 + br)*DPITCH + v0 + vc] = val;
    }
}

// Fused tf32 GEMM + epilogue. R15 structure (double-buffered fp16 staging,
// vectorized B-fill, 3 CTAs/SM) with fp16 bone matrices: G loads are
// 3x LDG.64 per bone (half the lane-bytes of fp32), unpacked on the fma/alu
// pipes which have headroom.
__global__ __launch_bounds__(256, 3)
void fused_kernel(const float* __restrict__ P,
                  const float* __restrict__ E,
                  float* __restrict__ out) {
    extern __shared__ __align__(16) char smem_raw[];
    uint32_t* sB = (uint32_t*)smem_raw;
    __half*   st0 = (__half*)(sB + SB_WORDS);

    const int tid   = threadIdx.x;
    const int lane  = tid & 31;
    const int wid   = tid >> 5;
    const int warpM = wid >> 2;      // 0..1
    const int warpN = wid & 3;       // 0..3
    const int cbase = blockIdx.x * NTILE;
    const int vbase = blockIdx.x * VTILE;

    // ---- fill full-K B tile [120 x 96] in fragment order (once) ----
    if (cbase + NTILE <= NV3) {
        for (int idx = tid; idx < KD*(NTILE/2); idx += 256) {
            int kl = idx / (NTILE/2);
            int c2 = idx - kl*(NTILE/2);
            int cl = c2*2;
            float2 v2 = make_float2(0.0f, 0.0f);
            if (kl < 63)
                v2 = *(const float2*)&P[(size_t)(kl+9)*NV3 + cbase + cl];
            else if (kl < 118)
                v2 = *(const float2*)&E[(size_t)(kl-63)*NV3 + cbase + cl];
            sB[bfrag_off(kl, cl)]     = to_tf32(v2.x);
            sB[bfrag_off(kl, cl + 1)] = to_tf32(v2.y);
        }
    } else {
        for (int idx = tid; idx < KD*NTILE; idx += 256) {
            int kl = idx / NTILE;
            int cl = idx - kl*NTILE;
            int c  = cbase + cl;
            float v = 0.0f;
            if (c < NV3) {
                if (kl < 63)       v = P[(size_t)(kl+9)*NV3 + c];
                else if (kl < 118) v = E[(size_t)(kl-63)*NV3 + c];
            }
            sB[bfrag_off(kl, cl)] = to_tf32(v);
        }
    }

    // epilogue thread mapping: 2 adjacent vertices x 4 rows
    const int vl2  = tid & 15;
    const int rgrp = tid >> 4;
    const int vp   = vbase + vl2*2;
    const bool valid = (vp < NV);

    __syncthreads();

    // ---- M-tile loop ----
    for (int mt = 0; mt < 4; mt++) {
        const uint32_t* Ag = g_coefA + mt*(MTILE*KD);
        const int Mbase = mt * MTILE;
        __half* st = st0 + (mt & 1) * ST_HALVES;

        float acc[2][3][4];
#pragma unroll
        for (int mi = 0; mi < 2; mi++)
#pragma unroll
            for (int ni = 0; ni < 3; ni++)
#pragma unroll
                for (int qq = 0; qq < 4; qq++) acc[mi][ni][qq] = 0.0f;

#pragma unroll
        for (int k8 = 0; k8 < 15; k8++) {
            uint32_t a[2][4];
#pragma unroll
            for (int mi = 0; mi < 2; mi++) {
                uint4 av = *(const uint4*)&Ag[((k8*4 + warpM*2 + mi)*32 + lane)*4];
                a[mi][0] = av.x; a[mi][1] = av.y; a[mi][2] = av.z; a[mi][3] = av.w;
            }
            uint32_t bf[3][2];
#pragma unroll
            for (int ni = 0; ni < 3; ni++) {
                uint2 bv = *(const uint2*)&sB[k8*(12*66) + (warpN*3 + ni)*66 + lane*2];
                bf[ni][0] = bv.x; bf[ni][1] = bv.y;
            }
#pragma unroll
            for (int mi = 0; mi < 2; mi++)
#pragma unroll
                for (int ni = 0; ni < 3; ni++) {
                    asm volatile(
                        "mma.sync.aligned.m16n8k8.row.col.f32.tf32.tf32.f32 "
                        "{%0,%1,%2,%3}, {%4,%5,%6,%7}, {%8,%9}, {%0,%1,%2,%3};"
                        : "+f"(acc[mi][ni][0]), "+f"(acc[mi][ni][1]),
                          "+f"(acc[mi][ni][2]), "+f"(acc[mi][ni][3])
                        : "r"(a[mi][0]), "r"(a[mi][1]), "r"(a[mi][2]), "r"(a[mi][3]),
                          "r"(bf[ni][0]), "r"(bf[ni][1]));
                }
        }

        // drain accumulators into this tile's staging buffer
        {
            const int gg  = lane >> 2;
            const int tt4 = lane & 3;
#pragma unroll
            for (int mi = 0; mi < 2; mi++) {
#pragma unroll
                for (int ni = 0; ni < 3; ni++) {
                    int row = warpM*32 + mi*16 + gg;
                    int col = warpN*24 + ni*8 + tt4*2;
                    *(__half2*)&st[row*ST_PITCH + col] =
                        __floats2half2_rn(acc[mi][ni][0], acc[mi][ni][1]);
                    *(__half2*)&st[(row+8)*ST_PITCH + col] =
                        __floats2half2_rn(acc[mi][ni][2], acc[mi][ni][3]);
                }
            }
        }
        __syncthreads();   // publish staging for this tile

        if (valid) {
            // packed per-vertex state: 4 LDG.128 per vertex (L1-hot for mt>0)
            float hT[2][3], hts[2][3], hw8[2][NB];
#pragma unroll
            for (int u = 0; u < 2; u++) {
                const float4* gv = (const float4*)&g_vert[(vp+u)*16];
                float4 a0 = gv[0], a1 = gv[1], a2 = gv[2], a3 = gv[3];
                hT[u][0] = a0.x; hT[u][1] = a0.y; hT[u][2] = a0.z;
                hts[u][0] = a1.x; hts[u][1] = a1.y; hts[u][2] = a1.z;
                hw8[u][0] = a2.x; hw8[u][1] = a2.y; hw8[u][2] = a2.z; hw8[u][3] = a2.w;
                hw8[u][4] = a3.x; hw8[u][5] = a3.y; hw8[u][6] = a3.z; hw8[u][7] = a3.w;
            }

            // epilogue: 4 rows x 2 vertices per thread
#pragma unroll
            for (int i = 0; i < 4; i++) {
                const int row = rgrp + i*16;
                const int b = Mbase + row;

                float2 dv = *(const float2*)&g_dist[(size_t)b*DPITCH + vp];

                const __half* sp = st + row*ST_PITCH + vl2*6;
                float2 f0 = __half22float2(*(const __half2*)(sp + 0));
                float2 f1 = __half22float2(*(const __half2*)(sp + 2));
                float2 f2 = __half22float2(*(const __half2*)(sp + 4));
                float cc[6] = {f0.x, f0.y, f1.x, f1.y, f2.x, f2.y};

                float px[2], py[2], pz[2], ox[2], oy[2], oz[2];
#pragma unroll
                for (int u = 0; u < 2; u++) {
                    float s = (u == 0) ? dv.x : dv.y;
                    px[u] = cc[u*3+0] + hT[u][0] + s*hts[u][0];
                    py[u] = cc[u*3+1] + hT[u][1] + s*hts[u][1];
                    pz[u] = cc[u*3+2] + hT[u][2] + s*hts[u][2];
                    ox[u] = 0.0f; oy[u] = 0.0f; oz[u] = 0.0f;
                }

                const uint2* Gh = (const uint2*)(g_boneH + b*(NB*12));
#pragma unroll
                for (int n = 0; n < NB; n++) {
                    // per bone: 3 LDG.64 (4 halves each = one 3x4 row)
                    uint2 r0 = Gh[n*3 + 0];
                    uint2 r1 = Gh[n*3 + 1];
                    uint2 r2 = Gh[n*3 + 2];
                    float2 g0a = __half22float2(*(const __half2*)&r0.x);
                    float2 g0b = __half22float2(*(const __half2*)&r0.y);
                    float2 g1a = __half22float2(*(const __half2*)&r1.x);
                    float2 g1b = __half22float2(*(const __half2*)&r1.y);
                    float2 g2a = __half22float2(*(const __half2*)&r2.x);
                    float2 g2b = __half22float2(*(const __half2*)&r2.y);
#pragma unroll
                    for (int u = 0; u < 2; u++) {
                        float wn = hw8[u][n];
                        ox[u] = fmaf(wn, fmaf(g0a.x, px[u], fmaf(g0a.y, py[u], fmaf(g0b.x, pz[u], g0b.y))), ox[u]);
                        oy[u] = fmaf(wn, fmaf(g1a.x, px[u], fmaf(g1a.y, py[u], fmaf(g1b.x, pz[u], g1b.y))), oy[u]);
                        oz[u] = fmaf(wn, fmaf(g2a.x, px[u], fmaf(g2a.y, py[u], fmaf(g2b.x, pz[u], g2b.y))), oz[u]);
                    }
                }

                size_t base = (size_t)b * NV3 + (size_t)vp * 3;   // even offset
                *(float2*)&out[base + 0] = make_float2(ox[0], oy[0]);
                *(float2*)&out[base + 2] = make_float2(oz[0], ox[1]);
                *(float2*)&out[base + 4] = make_float2(oy[1], oz[1]);
            }
        }
        // no trailing barrier: next drain targets the other staging buffer
    }
}

extern "C" void kernel_launch(void* const* d_in, const int* in_sizes, int n_in,
                              void* d_out, int out_size) {
    const float* theta  = (const float*)d_in[0];
    const float* tau    = (const float*)d_in[1];
    const float* alpha  = (const float*)d_in[2];
    const float* bsw    = (const float*)d_in[3];
    const float* W      = (const float*)d_in[4];
    const float* T      = (const float*)d_in[5];
    const float* P      = (const float*)d_in[6];
    const float* L      = (const float*)d_in[7];
    const float* ts     = (const float*)d_in[8];
    const float* L2P    = (const float*)d_in[9];
    const float* E      = (const float*)d_in[10];
    const float* uvgrid = (const float*)d_in[11];
    float* out = (float*)d_out;

    cudaFuncSetAttribute(fused_kernel,
                         cudaFuncAttributeMaxDynamicSharedMemorySize, SMEM_BYTES);

    prep_kernel<<<BATCH, 64>>>(theta, bsw, L2P);
    transpose_kernel<<<256, 256>>>(L);
    dist_kernel<<<NBLKS, 256>>>(uvgrid, tau, alpha, T, ts, W);

    fused_kernel<<<NBLKS, 256, SMEM_BYTES>>>(P, E, out);
}